// round 13
// baseline (speedup 1.0000x reference)
#include <cuda_runtime.h>
#include <math.h>

#define NLV 16
#define LOG2T 19
#define TMASK ((1u << LOG2T) - 1u)
#define P1 2654435761u
#define P2 805459861u

#define NBUCKET (1 << 18)      // 64^3 Morton buckets
#define MAXN (1 << 20)
#define SCAN_BLOCKS 256        // NBUCKET / 1024

__device__ int g_hist[NBUCKET];   // zero at entry (invariant, restored by scan_apply)
__device__ int g_off[NBUCKET];
__device__ int g_bsum[SCAN_BLOCKS];
__device__ int g_rank[MAXN];
__device__ float4 g_xs[MAXN];     // sorted coords + original index

struct LP {
    float g[NLV];   // grid = 2/res
    float ig[NLV];  // 1/grid = res/2
};

// ---------- Morton bucketing (6 bits/axis) ----------
__device__ __forceinline__ unsigned spread3(unsigned v) {
    v &= 0x3FF;
    v = (v | (v << 16)) & 0x030000FF;
    v = (v | (v << 8))  & 0x0300F00F;
    v = (v | (v << 4))  & 0x030C30C3;
    v = (v | (v << 2))  & 0x09249249;
    return v;
}

__device__ __forceinline__ unsigned morton_key(float xx, float xy, float xz) {
    float px = fminf(fmaxf(xx, -1.0f), 1.0f) + 1.0f;  // [0,2]
    float py = fminf(fmaxf(xy, -1.0f), 1.0f) + 1.0f;
    float pz = fminf(fmaxf(xz, -1.0f), 1.0f) + 1.0f;
    unsigned ix = min(63u, (unsigned)(px * 32.0f));
    unsigned iy = min(63u, (unsigned)(py * 32.0f));
    unsigned iz = min(63u, (unsigned)(pz * 32.0f));
    return (spread3(ix) << 2) | (spread3(iy) << 1) | spread3(iz);
}

// 4 points per thread; atomic returns intra-bucket rank (stored for scatter).
__global__ void hist_kernel(const float4* __restrict__ x4, int N) {
    int base = (blockIdx.x * 256 + threadIdx.x) * 4;
    if (base >= N) return;
    float4 q0 = __ldg(x4 + (size_t)base * 3 / 4 + 0);
    float4 q1 = __ldg(x4 + (size_t)base * 3 / 4 + 1);
    float4 q2 = __ldg(x4 + (size_t)base * 3 / 4 + 2);
    float c[12] = {q0.x,q0.y,q0.z,q0.w, q1.x,q1.y,q1.z,q1.w, q2.x,q2.y,q2.z,q2.w};
    int rank[4];
#pragma unroll
    for (int k = 0; k < 4; k++) {
        if (base + k < N)
            rank[k] = atomicAdd(&g_hist[morton_key(c[3*k], c[3*k+1], c[3*k+2])], 1);
    }
#pragma unroll
    for (int k = 0; k < 4; k++) {
        if (base + k < N)
            g_rank[base + k] = rank[k];
    }
}

// Block totals of g_hist: 256 blocks x 1024 threads.
__global__ void __launch_bounds__(1024) reduce_kernel() {
    int gid = blockIdx.x * 1024 + threadIdx.x;
    int v = g_hist[gid];
    int lane = threadIdx.x & 31, w = threadIdx.x >> 5;
#pragma unroll
    for (int d = 16; d >= 1; d >>= 1) v += __shfl_down_sync(0xFFFFFFFFu, v, d);
    __shared__ int part[32];
    if (lane == 0) part[w] = v;
    __syncthreads();
    if (w == 0) {
        int t = part[lane];
#pragma unroll
        for (int d = 16; d >= 1; d >>= 1) t += __shfl_down_sync(0xFFFFFFFFu, t, d);
        if (lane == 0) g_bsum[blockIdx.x] = t;
    }
}

// Exclusive scan; writes g_off, resets g_hist.
__global__ void __launch_bounds__(1024) scan_apply_kernel() {
    int bid = blockIdx.x;
    int gid = bid * 1024 + threadIdx.x;
    int v = g_hist[gid];
    g_hist[gid] = 0;

    int lane = threadIdx.x & 31, w = threadIdx.x >> 5;

    __shared__ int wsum[32];
    __shared__ int part[8];
    __shared__ int s_pre;

    int s = v;
#pragma unroll
    for (int d = 1; d < 32; d <<= 1) {
        int t = __shfl_up_sync(0xFFFFFFFFu, s, d);
        if (lane >= d) s += t;
    }
    if (lane == 31) wsum[w] = s;

    if (threadIdx.x < 256) {
        int t = (threadIdx.x < bid) ? g_bsum[threadIdx.x] : 0;
#pragma unroll
        for (int d = 16; d >= 1; d >>= 1) t += __shfl_down_sync(0xFFFFFFFFu, t, d);
        if (lane == 0) part[threadIdx.x >> 5] = t;
    }
    __syncthreads();

    if (w == 0) {
        int t = wsum[lane];
        int ss = t;
#pragma unroll
        for (int d = 1; d < 32; d <<= 1) {
            int u = __shfl_up_sync(0xFFFFFFFFu, ss, d);
            if (lane >= d) ss += u;
        }
        wsum[lane] = ss - t;
    }
    if (threadIdx.x == 512) {
        int t = 0;
#pragma unroll
        for (int i = 0; i < 8; i++) t += part[i];
        s_pre = t;
    }
    __syncthreads();

    g_off[gid] = (s - v) + wsum[w] + s_pre;
}

// Atomic-free scatter: recompute key; pos = off[key] + rank; 16B store only.
__global__ void scatter_kernel(const float4* __restrict__ x4, int N) {
    int base = (blockIdx.x * 256 + threadIdx.x) * 4;
    if (base >= N) return;
    float4 q0 = __ldg(x4 + (size_t)base * 3 / 4 + 0);
    float4 q1 = __ldg(x4 + (size_t)base * 3 / 4 + 1);
    float4 q2 = __ldg(x4 + (size_t)base * 3 / 4 + 2);
    float c[12] = {q0.x,q0.y,q0.z,q0.w, q1.x,q1.y,q1.z,q1.w, q2.x,q2.y,q2.z,q2.w};
    int4 rank4 = __ldg((const int4*)g_rank + (base >> 2));
    int rank[4] = {rank4.x, rank4.y, rank4.z, rank4.w};
    int pos[4];
#pragma unroll
    for (int k = 0; k < 4; k++) {
        if (base + k < N)
            pos[k] = __ldg(g_off + morton_key(c[3*k], c[3*k+1], c[3*k+2])) + rank[k];
    }
#pragma unroll
    for (int k = 0; k < 4; k++) {
        if (base + k < N)
            g_xs[pos[k]] = make_float4(c[3*k], c[3*k+1], c[3*k+2],
                                       __int_as_float(base + k));
    }
}

// L2-only gather (no L1 allocation) for fine levels.
__device__ __forceinline__ float2 ldcg_f2(const float2* p) {
    float2 r;
    asm volatile("ld.global.cg.v2.f32 {%0, %1}, [%2];"
                 : "=f"(r.x), "=f"(r.y) : "l"(p));
    return r;
}

// ---------- main encoder: R12 shape (2-col store staging), split cache policy ----------
__global__ void __launch_bounds__(256)
ingp_hash_kernel(const float* __restrict__ x,
                 const float2* __restrict__ emb,
                 float4* __restrict__ out,
                 int N, LP lp, int use_sorted)
{
    __shared__ float4 s0[256];   // 4KB: even pair of current flush group
    __shared__ float4 s1[256];   // 4KB: odd pair

    int i = blockIdx.x * 256 + threadIdx.x;
    int lane = threadIdx.x & 31;
    int wbase = threadIdx.x & ~31;
    bool active = (i < N);
    int idx = active ? i : (N > 0 ? N - 1 : 0);

    int n;
    float xx, xy, xz;
    if (use_sorted) {
        float4 v = __ldg(g_xs + idx);
        xx = v.x; xy = v.y; xz = v.z;
        n = active ? __float_as_int(v.w) : -1;
    } else {
        xx = __ldg(x + 3 * idx + 0);
        xy = __ldg(x + 3 * idx + 1);
        xz = __ldg(x + 3 * idx + 2);
        n = active ? idx : -1;
    }

    float px = fminf(fmaxf(xx, -1.0f), 1.0f) + 1.0f;
    float py = fminf(fmaxf(xy, -1.0f), 1.0f) + 1.0f;
    float pz = fminf(fmaxf(xz, -1.0f), 1.0f) + 1.0f;

    float2 prev = make_float2(0.0f, 0.0f);

#pragma unroll
    for (int l = 0; l < NLV; l++) {
        const float2* __restrict__ t = emb + ((size_t)l << LOG2T);
        float g  = lp.g[l];
        float ig = lp.ig[l];

        int bx = __float2int_rd(px * ig);
        int by = __float2int_rd(py * ig);
        int bz = __float2int_rd(pz * ig);
        float wx = fmaf(-(float)bx, g, px) * ig;
        float wy = fmaf(-(float)by, g, py) * ig;
        float wz = fmaf(-(float)bz, g, pz) * ig;

        unsigned hx0 = (unsigned)bx;
        unsigned hx1 = hx0 + 1u;
        unsigned hy0 = (unsigned)by * P1;
        unsigned hy1 = hy0 + P1;
        unsigned hz0 = (unsigned)bz * P2;
        unsigned hz1 = hz0 + P2;

        unsigned a00 = hx0 ^ hy0;
        unsigned a01 = hx0 ^ hy1;
        unsigned a10 = hx1 ^ hy0;
        unsigned a11 = hx1 ^ hy1;

        float2 e000, e001, e010, e011, e100, e101, e110, e111;
        if (l < 3) {   // coarse: small tables, keep L1-resident
            e000 = __ldg(t + ((a00 ^ hz0) & TMASK));
            e001 = __ldg(t + ((a00 ^ hz1) & TMASK));
            e010 = __ldg(t + ((a01 ^ hz0) & TMASK));
            e011 = __ldg(t + ((a01 ^ hz1) & TMASK));
            e100 = __ldg(t + ((a10 ^ hz0) & TMASK));
            e101 = __ldg(t + ((a10 ^ hz1) & TMASK));
            e110 = __ldg(t + ((a11 ^ hz0) & TMASK));
            e111 = __ldg(t + ((a11 ^ hz1) & TMASK));
        } else {       // fine: L2-only, don't thrash L1D
            e000 = ldcg_f2(t + ((a00 ^ hz0) & TMASK));
            e001 = ldcg_f2(t + ((a00 ^ hz1) & TMASK));
            e010 = ldcg_f2(t + ((a01 ^ hz0) & TMASK));
            e011 = ldcg_f2(t + ((a01 ^ hz1) & TMASK));
            e100 = ldcg_f2(t + ((a10 ^ hz0) & TMASK));
            e101 = ldcg_f2(t + ((a10 ^ hz1) & TMASK));
            e110 = ldcg_f2(t + ((a11 ^ hz0) & TMASK));
            e111 = ldcg_f2(t + ((a11 ^ hz1) & TMASK));
        }

        float ux = 1.0f - wx;
        float uy = 1.0f - wy;
        float uz = 1.0f - wz;

        float s00 = uy * uz;
        float s01 = uy * wz;
        float s10 = wy * uz;
        float s11 = wy * wz;

        float w000 = ux * s00, w001 = ux * s01, w010 = ux * s10, w011 = ux * s11;
        float w100 = wx * s00, w101 = wx * s01, w110 = wx * s10, w111 = wx * s11;

        float rx = w000 * e000.x;
        float ry = w000 * e000.y;
        rx = fmaf(w001, e001.x, rx); ry = fmaf(w001, e001.y, ry);
        rx = fmaf(w010, e010.x, rx); ry = fmaf(w010, e010.y, ry);
        rx = fmaf(w011, e011.x, rx); ry = fmaf(w011, e011.y, ry);
        rx = fmaf(w100, e100.x, rx); ry = fmaf(w100, e100.y, ry);
        rx = fmaf(w101, e101.x, rx); ry = fmaf(w101, e101.y, ry);
        rx = fmaf(w110, e110.x, rx); ry = fmaf(w110, e110.y, ry);
        rx = fmaf(w111, e111.x, rx); ry = fmaf(w111, e111.y, ry);

        if (l & 1) {
            float4 rv = make_float4(prev.x, prev.y, rx, ry);
            if (((l >> 1) & 1) == 0) {
                s0[threadIdx.x] = rv;      // even output column of this group
            } else {
                s1[threadIdx.x] = rv;      // odd column -> flush the group
                int f = l >> 2;            // flush group index 0..3 (cols 2f, 2f+1)
                __syncwarp();
                int j = lane & 1;
                int h = lane >> 1;         // 0..15
                int na = __shfl_sync(0xFFFFFFFFu, n, h);
                int nb = __shfl_sync(0xFFFFFFFFu, n, 16 + h);
                float4 va = j ? s1[wbase + h]      : s0[wbase + h];
                float4 vb = j ? s1[wbase + 16 + h] : s0[wbase + 16 + h];
                if (na >= 0) __stcs(out + (size_t)na * 8 + 2 * f + j, va);
                if (nb >= 0) __stcs(out + (size_t)nb * 8 + 2 * f + j, vb);
                __syncwarp();
            }
        } else {
            prev.x = rx;
            prev.y = ry;
        }
    }
}

extern "C" void kernel_launch(void* const* d_in, const int* in_sizes, int n_in,
                              void* d_out, int out_size)
{
    const float*  x   = (const float*)d_in[0];
    const float2* emb = (const float2*)d_in[1];
    int N = in_sizes[0] / 3;

    LP lp;
    double b = exp((log(512.0) - log(16.0)) / 15.0);
    for (int l = 0; l < NLV; l++) {
        float r = (float)floor(16.0 * pow(b, (double)l));
        lp.g[l]  = 2.0f / r;
        lp.ig[l] = r * 0.5f;
    }

    if (N <= 0) return;
    int blocks = (N + 255) / 256;

    if (N <= MAXN && (N & 3) == 0) {
        int qblocks = (N / 4 + 255) / 256;
        hist_kernel<<<qblocks, 256>>>((const float4*)x, N);
        reduce_kernel<<<SCAN_BLOCKS, 1024>>>();
        scan_apply_kernel<<<SCAN_BLOCKS, 1024>>>();
        scatter_kernel<<<qblocks, 256>>>((const float4*)x, N);
        ingp_hash_kernel<<<blocks, 256>>>(x, emb, (float4*)d_out, N, lp, 1);
    } else {
        ingp_hash_kernel<<<blocks, 256>>>(x, emb, (float4*)d_out, N, lp, 0);
    }
}

// round 14
// speedup vs baseline: 1.0422x; 1.0422x over previous
#include <cuda_runtime.h>
#include <math.h>

#define NLV 16
#define LOG2T 19
#define TMASK ((1u << LOG2T) - 1u)
#define P1 2654435761u
#define P2 805459861u

#define NBUCKET (1 << 18)      // 64^3 Morton buckets
#define MAXN (1 << 20)
#define SCAN_BLOCKS 256        // NBUCKET / 1024

__device__ int g_hist[NBUCKET];   // zero at entry (invariant, restored by scan_apply)
__device__ int g_off[NBUCKET];
__device__ int g_bsum[SCAN_BLOCKS];
__device__ int g_key[MAXN];
__device__ int g_rank[MAXN];
__device__ float4 g_xs[MAXN];     // sorted coords + original index

struct LP {
    float g[NLV];   // grid = 2/res
    float ig[NLV];  // 1/grid = res/2
};

// ---------- Morton bucketing (6 bits/axis) ----------
__device__ __forceinline__ unsigned spread3(unsigned v) {
    v &= 0x3FF;
    v = (v | (v << 16)) & 0x030000FF;
    v = (v | (v << 8))  & 0x0300F00F;
    v = (v | (v << 4))  & 0x030C30C3;
    v = (v | (v << 2))  & 0x09249249;
    return v;
}

__device__ __forceinline__ unsigned morton_key(float xx, float xy, float xz) {
    float px = fminf(fmaxf(xx, -1.0f), 1.0f) + 1.0f;  // [0,2]
    float py = fminf(fmaxf(xy, -1.0f), 1.0f) + 1.0f;
    float pz = fminf(fmaxf(xz, -1.0f), 1.0f) + 1.0f;
    unsigned ix = min(63u, (unsigned)(px * 32.0f));
    unsigned iy = min(63u, (unsigned)(py * 32.0f));
    unsigned iz = min(63u, (unsigned)(pz * 32.0f));
    return (spread3(ix) << 2) | (spread3(iy) << 1) | spread3(iz);
}

// 4 points per thread; atomic returns intra-bucket rank (stored for scatter).
__global__ void hist_kernel(const float4* __restrict__ x4, int N) {
    int base = (blockIdx.x * 256 + threadIdx.x) * 4;
    if (base >= N) return;
    float4 q0 = __ldg(x4 + (size_t)base * 3 / 4 + 0);
    float4 q1 = __ldg(x4 + (size_t)base * 3 / 4 + 1);
    float4 q2 = __ldg(x4 + (size_t)base * 3 / 4 + 2);
    float c[12] = {q0.x,q0.y,q0.z,q0.w, q1.x,q1.y,q1.z,q1.w, q2.x,q2.y,q2.z,q2.w};
    int key[4], rank[4];
#pragma unroll
    for (int k = 0; k < 4; k++) {
        if (base + k < N) {
            key[k] = (int)morton_key(c[3*k], c[3*k+1], c[3*k+2]);
            rank[k] = atomicAdd(&g_hist[key[k]], 1);
        }
    }
#pragma unroll
    for (int k = 0; k < 4; k++) {
        if (base + k < N) {
            g_key[base + k] = key[k];
            g_rank[base + k] = rank[k];
        }
    }
}

// Block totals of g_hist: 256 blocks x 1024 threads.
__global__ void __launch_bounds__(1024) reduce_kernel() {
    int gid = blockIdx.x * 1024 + threadIdx.x;
    int v = g_hist[gid];
    int lane = threadIdx.x & 31, w = threadIdx.x >> 5;
#pragma unroll
    for (int d = 16; d >= 1; d >>= 1) v += __shfl_down_sync(0xFFFFFFFFu, v, d);
    __shared__ int part[32];
    if (lane == 0) part[w] = v;
    __syncthreads();
    if (w == 0) {
        int t = part[lane];
#pragma unroll
        for (int d = 16; d >= 1; d >>= 1) t += __shfl_down_sync(0xFFFFFFFFu, t, d);
        if (lane == 0) g_bsum[blockIdx.x] = t;
    }
}

// Exclusive scan; writes g_off, resets g_hist.
__global__ void __launch_bounds__(1024) scan_apply_kernel() {
    int bid = blockIdx.x;
    int gid = bid * 1024 + threadIdx.x;
    int v = g_hist[gid];
    g_hist[gid] = 0;

    int lane = threadIdx.x & 31, w = threadIdx.x >> 5;

    __shared__ int wsum[32];
    __shared__ int part[8];
    __shared__ int s_pre;

    int s = v;
#pragma unroll
    for (int d = 1; d < 32; d <<= 1) {
        int t = __shfl_up_sync(0xFFFFFFFFu, s, d);
        if (lane >= d) s += t;
    }
    if (lane == 31) wsum[w] = s;

    if (threadIdx.x < 256) {
        int t = (threadIdx.x < bid) ? g_bsum[threadIdx.x] : 0;
#pragma unroll
        for (int d = 16; d >= 1; d >>= 1) t += __shfl_down_sync(0xFFFFFFFFu, t, d);
        if (lane == 0) part[threadIdx.x >> 5] = t;
    }
    __syncthreads();

    if (w == 0) {
        int t = wsum[lane];
        int ss = t;
#pragma unroll
        for (int d = 1; d < 32; d <<= 1) {
            int u = __shfl_up_sync(0xFFFFFFFFu, ss, d);
            if (lane >= d) ss += u;
        }
        wsum[lane] = ss - t;
    }
    if (threadIdx.x == 512) {
        int t = 0;
#pragma unroll
        for (int i = 0; i < 8; i++) t += part[i];
        s_pre = t;
    }
    __syncthreads();

    g_off[gid] = (s - v) + wsum[w] + s_pre;
}

// Atomic-free scatter: pos = off[key] + rank; scattered 16B store only.
__global__ void scatter_kernel(const float4* __restrict__ x4, int N) {
    int base = (blockIdx.x * 256 + threadIdx.x) * 4;
    if (base >= N) return;
    float4 q0 = __ldg(x4 + (size_t)base * 3 / 4 + 0);
    float4 q1 = __ldg(x4 + (size_t)base * 3 / 4 + 1);
    float4 q2 = __ldg(x4 + (size_t)base * 3 / 4 + 2);
    float c[12] = {q0.x,q0.y,q0.z,q0.w, q1.x,q1.y,q1.z,q1.w, q2.x,q2.y,q2.z,q2.w};
    int4 key4  = __ldg((const int4*)g_key  + (base >> 2));
    int4 rank4 = __ldg((const int4*)g_rank + (base >> 2));
    int key[4]  = {key4.x, key4.y, key4.z, key4.w};
    int rank[4] = {rank4.x, rank4.y, rank4.z, rank4.w};
    int pos[4];
#pragma unroll
    for (int k = 0; k < 4; k++) {
        if (base + k < N)
            pos[k] = __ldg(g_off + key[k]) + rank[k];
    }
#pragma unroll
    for (int k = 0; k < 4; k++) {
        if (base + k < N)
            g_xs[pos[k]] = make_float4(c[3*k], c[3*k+1], c[3*k+2],
                                       __int_as_float(base + k));
    }
}

// Evict-first streaming gather for the finest levels.
__device__ __forceinline__ float2 ldcs_f2(const float2* p) {
    float2 r;
    asm volatile("ld.global.cs.v2.f32 {%0, %1}, [%2];"
                 : "=f"(r.x), "=f"(r.y) : "l"(p));
    return r;
}

// ---------- main encoder: R12 shape, streaming hint for levels >= 12 ----------
__global__ void __launch_bounds__(256)
ingp_hash_kernel(const float* __restrict__ x,
                 const float2* __restrict__ emb,
                 float4* __restrict__ out,
                 int N, LP lp, int use_sorted)
{
    __shared__ float4 s0[256];   // 4KB: even pair of current flush group
    __shared__ float4 s1[256];   // 4KB: odd pair

    int i = blockIdx.x * 256 + threadIdx.x;
    int lane = threadIdx.x & 31;
    int wbase = threadIdx.x & ~31;
    bool active = (i < N);
    int idx = active ? i : (N > 0 ? N - 1 : 0);

    int n;
    float xx, xy, xz;
    if (use_sorted) {
        float4 v = __ldg(g_xs + idx);
        xx = v.x; xy = v.y; xz = v.z;
        n = active ? __float_as_int(v.w) : -1;
    } else {
        xx = __ldg(x + 3 * idx + 0);
        xy = __ldg(x + 3 * idx + 1);
        xz = __ldg(x + 3 * idx + 2);
        n = active ? idx : -1;
    }

    float px = fminf(fmaxf(xx, -1.0f), 1.0f) + 1.0f;
    float py = fminf(fmaxf(xy, -1.0f), 1.0f) + 1.0f;
    float pz = fminf(fmaxf(xz, -1.0f), 1.0f) + 1.0f;

    float2 prev = make_float2(0.0f, 0.0f);

#pragma unroll
    for (int l = 0; l < NLV; l++) {
        const float2* __restrict__ t = emb + ((size_t)l << LOG2T);
        float g  = lp.g[l];
        float ig = lp.ig[l];

        int bx = __float2int_rd(px * ig);
        int by = __float2int_rd(py * ig);
        int bz = __float2int_rd(pz * ig);
        float wx = fmaf(-(float)bx, g, px) * ig;
        float wy = fmaf(-(float)by, g, py) * ig;
        float wz = fmaf(-(float)bz, g, pz) * ig;

        unsigned hx0 = (unsigned)bx;
        unsigned hx1 = hx0 + 1u;
        unsigned hy0 = (unsigned)by * P1;
        unsigned hy1 = hy0 + P1;
        unsigned hz0 = (unsigned)bz * P2;
        unsigned hz1 = hz0 + P2;

        unsigned a00 = hx0 ^ hy0;
        unsigned a01 = hx0 ^ hy1;
        unsigned a10 = hx1 ^ hy0;
        unsigned a11 = hx1 ^ hy1;

        float2 e000, e001, e010, e011, e100, e101, e110, e111;
        if (l < 12) {  // default policy: L1-resident (proven best for 0-11)
            e000 = __ldg(t + ((a00 ^ hz0) & TMASK));
            e001 = __ldg(t + ((a00 ^ hz1) & TMASK));
            e010 = __ldg(t + ((a01 ^ hz0) & TMASK));
            e011 = __ldg(t + ((a01 ^ hz1) & TMASK));
            e100 = __ldg(t + ((a10 ^ hz0) & TMASK));
            e101 = __ldg(t + ((a10 ^ hz1) & TMASK));
            e110 = __ldg(t + ((a11 ^ hz0) & TMASK));
            e111 = __ldg(t + ((a11 ^ hz1) & TMASK));
        } else {       // finest: evict-first, minimize L1 displacement
            e000 = ldcs_f2(t + ((a00 ^ hz0) & TMASK));
            e001 = ldcs_f2(t + ((a00 ^ hz1) & TMASK));
            e010 = ldcs_f2(t + ((a01 ^ hz0) & TMASK));
            e011 = ldcs_f2(t + ((a01 ^ hz1) & TMASK));
            e100 = ldcs_f2(t + ((a10 ^ hz0) & TMASK));
            e101 = ldcs_f2(t + ((a10 ^ hz1) & TMASK));
            e110 = ldcs_f2(t + ((a11 ^ hz0) & TMASK));
            e111 = ldcs_f2(t + ((a11 ^ hz1) & TMASK));
        }

        float ux = 1.0f - wx;
        float uy = 1.0f - wy;
        float uz = 1.0f - wz;

        float s00 = uy * uz;
        float s01 = uy * wz;
        float s10 = wy * uz;
        float s11 = wy * wz;

        float w000 = ux * s00, w001 = ux * s01, w010 = ux * s10, w011 = ux * s11;
        float w100 = wx * s00, w101 = wx * s01, w110 = wx * s10, w111 = wx * s11;

        float rx = w000 * e000.x;
        float ry = w000 * e000.y;
        rx = fmaf(w001, e001.x, rx); ry = fmaf(w001, e001.y, ry);
        rx = fmaf(w010, e010.x, rx); ry = fmaf(w010, e010.y, ry);
        rx = fmaf(w011, e011.x, rx); ry = fmaf(w011, e011.y, ry);
        rx = fmaf(w100, e100.x, rx); ry = fmaf(w100, e100.y, ry);
        rx = fmaf(w101, e101.x, rx); ry = fmaf(w101, e101.y, ry);
        rx = fmaf(w110, e110.x, rx); ry = fmaf(w110, e110.y, ry);
        rx = fmaf(w111, e111.x, rx); ry = fmaf(w111, e111.y, ry);

        if (l & 1) {
            float4 rv = make_float4(prev.x, prev.y, rx, ry);
            if (((l >> 1) & 1) == 0) {
                s0[threadIdx.x] = rv;      // even output column of this group
            } else {
                s1[threadIdx.x] = rv;      // odd column -> flush the group
                int f = l >> 2;            // flush group index 0..3 (cols 2f, 2f+1)
                __syncwarp();
                int j = lane & 1;
                int h = lane >> 1;         // 0..15
                int na = __shfl_sync(0xFFFFFFFFu, n, h);
                int nb = __shfl_sync(0xFFFFFFFFu, n, 16 + h);
                float4 va = j ? s1[wbase + h]      : s0[wbase + h];
                float4 vb = j ? s1[wbase + 16 + h] : s0[wbase + 16 + h];
                if (na >= 0) __stcs(out + (size_t)na * 8 + 2 * f + j, va);
                if (nb >= 0) __stcs(out + (size_t)nb * 8 + 2 * f + j, vb);
                __syncwarp();
            }
        } else {
            prev.x = rx;
            prev.y = ry;
        }
    }
}

extern "C" void kernel_launch(void* const* d_in, const int* in_sizes, int n_in,
                              void* d_out, int out_size)
{
    const float*  x   = (const float*)d_in[0];
    const float2* emb = (const float2*)d_in[1];
    int N = in_sizes[0] / 3;

    LP lp;
    double b = exp((log(512.0) - log(16.0)) / 15.0);
    for (int l = 0; l < NLV; l++) {
        float r = (float)floor(16.0 * pow(b, (double)l));
        lp.g[l]  = 2.0f / r;
        lp.ig[l] = r * 0.5f;
    }

    if (N <= 0) return;
    int blocks = (N + 255) / 256;

    if (N <= MAXN && (N & 3) == 0) {
        int qblocks = (N / 4 + 255) / 256;
        hist_kernel<<<qblocks, 256>>>((const float4*)x, N);
        reduce_kernel<<<SCAN_BLOCKS, 1024>>>();
        scan_apply_kernel<<<SCAN_BLOCKS, 1024>>>();
        scatter_kernel<<<qblocks, 256>>>((const float4*)x, N);
        ingp_hash_kernel<<<blocks, 256>>>(x, emb, (float4*)d_out, N, lp, 1);
    } else {
        ingp_hash_kernel<<<blocks, 256>>>(x, emb, (float4*)d_out, N, lp, 0);
    }
}

// round 15
// speedup vs baseline: 1.1933x; 1.1449x over previous
#include <cuda_runtime.h>
#include <math.h>

#define NLV 16
#define LOG2T 19
#define TMASK ((1u << LOG2T) - 1u)
#define P1 2654435761u
#define P2 805459861u

#define NBUCKET (1 << 18)      // 64^3 Morton buckets
#define MAXN (1 << 20)
#define SCAN_BLOCKS 256        // NBUCKET / 1024

__device__ int g_hist[NBUCKET];   // zero at entry (invariant, restored by scan_apply)
__device__ int g_off[NBUCKET];
__device__ int g_bsum[SCAN_BLOCKS];
__device__ int g_rank[MAXN];
__device__ float4 g_xs[MAXN];     // sorted coords + original index

struct LP {
    float g[NLV];   // grid = 2/res
    float ig[NLV];  // 1/grid = res/2
};

// ---------- Morton bucketing (6 bits/axis) ----------
__device__ __forceinline__ unsigned spread3(unsigned v) {
    v &= 0x3FF;
    v = (v | (v << 16)) & 0x030000FF;
    v = (v | (v << 8))  & 0x0300F00F;
    v = (v | (v << 4))  & 0x030C30C3;
    v = (v | (v << 2))  & 0x09249249;
    return v;
}

__device__ __forceinline__ unsigned morton_key(float xx, float xy, float xz) {
    float px = fminf(fmaxf(xx, -1.0f), 1.0f) + 1.0f;  // [0,2]
    float py = fminf(fmaxf(xy, -1.0f), 1.0f) + 1.0f;
    float pz = fminf(fmaxf(xz, -1.0f), 1.0f) + 1.0f;
    unsigned ix = min(63u, (unsigned)(px * 32.0f));
    unsigned iy = min(63u, (unsigned)(py * 32.0f));
    unsigned iz = min(63u, (unsigned)(pz * 32.0f));
    return (spread3(ix) << 2) | (spread3(iy) << 1) | spread3(iz);
}

// 4 points per thread; atomic returns intra-bucket rank (stored for scatter).
__global__ void hist_kernel(const float4* __restrict__ x4, int N) {
    int base = (blockIdx.x * 256 + threadIdx.x) * 4;
    if (base >= N) return;
    float4 q0 = __ldg(x4 + (size_t)base * 3 / 4 + 0);
    float4 q1 = __ldg(x4 + (size_t)base * 3 / 4 + 1);
    float4 q2 = __ldg(x4 + (size_t)base * 3 / 4 + 2);
    float c[12] = {q0.x,q0.y,q0.z,q0.w, q1.x,q1.y,q1.z,q1.w, q2.x,q2.y,q2.z,q2.w};
    int rank[4];
#pragma unroll
    for (int k = 0; k < 4; k++) {
        if (base + k < N)
            rank[k] = atomicAdd(&g_hist[morton_key(c[3*k], c[3*k+1], c[3*k+2])], 1);
    }
#pragma unroll
    for (int k = 0; k < 4; k++) {
        if (base + k < N)
            g_rank[base + k] = rank[k];
    }
}

// Block totals of g_hist: 256 blocks x 1024 threads.
__global__ void __launch_bounds__(1024) reduce_kernel() {
    int gid = blockIdx.x * 1024 + threadIdx.x;
    int v = g_hist[gid];
    int lane = threadIdx.x & 31, w = threadIdx.x >> 5;
#pragma unroll
    for (int d = 16; d >= 1; d >>= 1) v += __shfl_down_sync(0xFFFFFFFFu, v, d);
    __shared__ int part[32];
    if (lane == 0) part[w] = v;
    __syncthreads();
    if (w == 0) {
        int t = part[lane];
#pragma unroll
        for (int d = 16; d >= 1; d >>= 1) t += __shfl_down_sync(0xFFFFFFFFu, t, d);
        if (lane == 0) g_bsum[blockIdx.x] = t;
    }
}

// Exclusive scan; writes g_off, resets g_hist.
__global__ void __launch_bounds__(1024) scan_apply_kernel() {
    int bid = blockIdx.x;
    int gid = bid * 1024 + threadIdx.x;
    int v = g_hist[gid];
    g_hist[gid] = 0;

    int lane = threadIdx.x & 31, w = threadIdx.x >> 5;

    __shared__ int wsum[32];
    __shared__ int part[8];
    __shared__ int s_pre;

    int s = v;
#pragma unroll
    for (int d = 1; d < 32; d <<= 1) {
        int t = __shfl_up_sync(0xFFFFFFFFu, s, d);
        if (lane >= d) s += t;
    }
    if (lane == 31) wsum[w] = s;

    if (threadIdx.x < 256) {
        int t = (threadIdx.x < bid) ? g_bsum[threadIdx.x] : 0;
#pragma unroll
        for (int d = 16; d >= 1; d >>= 1) t += __shfl_down_sync(0xFFFFFFFFu, t, d);
        if (lane == 0) part[threadIdx.x >> 5] = t;
    }
    __syncthreads();

    if (w == 0) {
        int t = wsum[lane];
        int ss = t;
#pragma unroll
        for (int d = 1; d < 32; d <<= 1) {
            int u = __shfl_up_sync(0xFFFFFFFFu, ss, d);
            if (lane >= d) ss += u;
        }
        wsum[lane] = ss - t;
    }
    if (threadIdx.x == 512) {
        int t = 0;
#pragma unroll
        for (int i = 0; i < 8; i++) t += part[i];
        s_pre = t;
    }
    __syncthreads();

    g_off[gid] = (s - v) + wsum[w] + s_pre;
}

// Atomic-free scatter: recompute key; pos = off[key] + rank; 16B store only.
__global__ void scatter_kernel(const float4* __restrict__ x4, int N) {
    int base = (blockIdx.x * 256 + threadIdx.x) * 4;
    if (base >= N) return;
    float4 q0 = __ldg(x4 + (size_t)base * 3 / 4 + 0);
    float4 q1 = __ldg(x4 + (size_t)base * 3 / 4 + 1);
    float4 q2 = __ldg(x4 + (size_t)base * 3 / 4 + 2);
    float c[12] = {q0.x,q0.y,q0.z,q0.w, q1.x,q1.y,q1.z,q1.w, q2.x,q2.y,q2.z,q2.w};
    int4 rank4 = __ldg((const int4*)g_rank + (base >> 2));
    int rank[4] = {rank4.x, rank4.y, rank4.z, rank4.w};
    int pos[4];
#pragma unroll
    for (int k = 0; k < 4; k++) {
        if (base + k < N)
            pos[k] = __ldg(g_off + morton_key(c[3*k], c[3*k+1], c[3*k+2])) + rank[k];
    }
#pragma unroll
    for (int k = 0; k < 4; k++) {
        if (base + k < N)
            g_xs[pos[k]] = make_float4(c[3*k], c[3*k+1], c[3*k+2],
                                       __int_as_float(base + k));
    }
}

// ---------- main encoder: R12 exact (default caching, 2-col store staging) ----------
__global__ void __launch_bounds__(256)
ingp_hash_kernel(const float* __restrict__ x,
                 const float2* __restrict__ emb,
                 float4* __restrict__ out,
                 int N, LP lp, int use_sorted)
{
    __shared__ float4 s0[256];   // 4KB: even pair of current flush group
    __shared__ float4 s1[256];   // 4KB: odd pair

    int i = blockIdx.x * 256 + threadIdx.x;
    int lane = threadIdx.x & 31;
    int wbase = threadIdx.x & ~31;
    bool active = (i < N);
    int idx = active ? i : (N > 0 ? N - 1 : 0);

    int n;
    float xx, xy, xz;
    if (use_sorted) {
        float4 v = __ldg(g_xs + idx);
        xx = v.x; xy = v.y; xz = v.z;
        n = active ? __float_as_int(v.w) : -1;
    } else {
        xx = __ldg(x + 3 * idx + 0);
        xy = __ldg(x + 3 * idx + 1);
        xz = __ldg(x + 3 * idx + 2);
        n = active ? idx : -1;
    }

    float px = fminf(fmaxf(xx, -1.0f), 1.0f) + 1.0f;
    float py = fminf(fmaxf(xy, -1.0f), 1.0f) + 1.0f;
    float pz = fminf(fmaxf(xz, -1.0f), 1.0f) + 1.0f;

    float2 prev = make_float2(0.0f, 0.0f);

#pragma unroll
    for (int l = 0; l < NLV; l++) {
        const float2* __restrict__ t = emb + ((size_t)l << LOG2T);
        float g  = lp.g[l];
        float ig = lp.ig[l];

        int bx = __float2int_rd(px * ig);
        int by = __float2int_rd(py * ig);
        int bz = __float2int_rd(pz * ig);
        float wx = fmaf(-(float)bx, g, px) * ig;
        float wy = fmaf(-(float)by, g, py) * ig;
        float wz = fmaf(-(float)bz, g, pz) * ig;

        unsigned hx0 = (unsigned)bx;
        unsigned hx1 = hx0 + 1u;
        unsigned hy0 = (unsigned)by * P1;
        unsigned hy1 = hy0 + P1;
        unsigned hz0 = (unsigned)bz * P2;
        unsigned hz1 = hz0 + P2;

        unsigned a00 = hx0 ^ hy0;
        unsigned a01 = hx0 ^ hy1;
        unsigned a10 = hx1 ^ hy0;
        unsigned a11 = hx1 ^ hy1;

        float2 e000 = __ldg(t + ((a00 ^ hz0) & TMASK));
        float2 e001 = __ldg(t + ((a00 ^ hz1) & TMASK));
        float2 e010 = __ldg(t + ((a01 ^ hz0) & TMASK));
        float2 e011 = __ldg(t + ((a01 ^ hz1) & TMASK));
        float2 e100 = __ldg(t + ((a10 ^ hz0) & TMASK));
        float2 e101 = __ldg(t + ((a10 ^ hz1) & TMASK));
        float2 e110 = __ldg(t + ((a11 ^ hz0) & TMASK));
        float2 e111 = __ldg(t + ((a11 ^ hz1) & TMASK));

        float ux = 1.0f - wx;
        float uy = 1.0f - wy;
        float uz = 1.0f - wz;

        float s00 = uy * uz;
        float s01 = uy * wz;
        float s10 = wy * uz;
        float s11 = wy * wz;

        float w000 = ux * s00, w001 = ux * s01, w010 = ux * s10, w011 = ux * s11;
        float w100 = wx * s00, w101 = wx * s01, w110 = wx * s10, w111 = wx * s11;

        float rx = w000 * e000.x;
        float ry = w000 * e000.y;
        rx = fmaf(w001, e001.x, rx); ry = fmaf(w001, e001.y, ry);
        rx = fmaf(w010, e010.x, rx); ry = fmaf(w010, e010.y, ry);
        rx = fmaf(w011, e011.x, rx); ry = fmaf(w011, e011.y, ry);
        rx = fmaf(w100, e100.x, rx); ry = fmaf(w100, e100.y, ry);
        rx = fmaf(w101, e101.x, rx); ry = fmaf(w101, e101.y, ry);
        rx = fmaf(w110, e110.x, rx); ry = fmaf(w110, e110.y, ry);
        rx = fmaf(w111, e111.x, rx); ry = fmaf(w111, e111.y, ry);

        if (l & 1) {
            float4 rv = make_float4(prev.x, prev.y, rx, ry);
            if (((l >> 1) & 1) == 0) {
                s0[threadIdx.x] = rv;      // even output column of this group
            } else {
                s1[threadIdx.x] = rv;      // odd column -> flush the group
                int f = l >> 2;            // flush group index 0..3 (cols 2f, 2f+1)
                __syncwarp();
                int j = lane & 1;
                int h = lane >> 1;         // 0..15
                int na = __shfl_sync(0xFFFFFFFFu, n, h);
                int nb = __shfl_sync(0xFFFFFFFFu, n, 16 + h);
                float4 va = j ? s1[wbase + h]      : s0[wbase + h];
                float4 vb = j ? s1[wbase + 16 + h] : s0[wbase + 16 + h];
                if (na >= 0) __stcs(out + (size_t)na * 8 + 2 * f + j, va);
                if (nb >= 0) __stcs(out + (size_t)nb * 8 + 2 * f + j, vb);
                __syncwarp();
            }
        } else {
            prev.x = rx;
            prev.y = ry;
        }
    }
}

extern "C" void kernel_launch(void* const* d_in, const int* in_sizes, int n_in,
                              void* d_out, int out_size)
{
    const float*  x   = (const float*)d_in[0];
    const float2* emb = (const float2*)d_in[1];
    int N = in_sizes[0] / 3;

    LP lp;
    double b = exp((log(512.0) - log(16.0)) / 15.0);
    for (int l = 0; l < NLV; l++) {
        float r = (float)floor(16.0 * pow(b, (double)l));
        lp.g[l]  = 2.0f / r;
        lp.ig[l] = r * 0.5f;
    }

    if (N <= 0) return;
    int blocks = (N + 255) / 256;

    if (N <= MAXN && (N & 3) == 0) {
        int qblocks = (N / 4 + 255) / 256;
        hist_kernel<<<qblocks, 256>>>((const float4*)x, N);
        reduce_kernel<<<SCAN_BLOCKS, 1024>>>();
        scan_apply_kernel<<<SCAN_BLOCKS, 1024>>>();
        scatter_kernel<<<qblocks, 256>>>((const float4*)x, N);
        ingp_hash_kernel<<<blocks, 256>>>(x, emb, (float4*)d_out, N, lp, 1);
    } else {
        ingp_hash_kernel<<<blocks, 256>>>(x, emb, (float4*)d_out, N, lp, 0);
    }
}